// round 1
// baseline (speedup 1.0000x reference)
#include <cuda_runtime.h>
#include <cuda_bf16.h>
#include <math.h>
#include <stdint.h>

#define B_  64
#define E_  512
#define H_  512
#define V_  32000
#define T_  32
#define G4  2048   // 4*H

// ---------------- persistent device state ----------------
__device__ float g_h[2][B_ * H_];          // double-buffered hidden state, [parity][b*512+j]
__device__ float g_c[B_ * H_];             // cell state
__device__ float g_gates[2][B_ * G4];      // [khalf][b*2048 + r] partial gate pre-activations
__device__ unsigned long long g_amax[2][B_]; // double-buffered packed argmax accumulators

// ordered-float key: monotonic float -> uint32 mapping
__device__ __forceinline__ unsigned fkey(float f) {
    unsigned u = __float_as_uint(f);
    return (u & 0x80000000u) ? ~u : (u | 0x80000000u);
}

// =========================================================
// K1a: gate pre-activations.
//   khalf=0: x @ W_ih^T   (x = embed_W[tok])
//   khalf=1: h @ W_hh^T
// grid (64, 2), 256 threads. Block = 32 rows x 64 batch, K=512.
// Thread tile: 2 rows x 4 batch.
// =========================================================
__global__ __launch_bounds__(256) void k_gates(
    int t,
    const float* __restrict__ features,
    const void*  __restrict__ captions,
    const float* __restrict__ embed,
    const float* __restrict__ W_ih,
    const float* __restrict__ W_hh)
{
    __shared__ float acts[128][68];   // [kk][b] transposed activation chunk (padded)
    __shared__ int   stok[B_];

    const int khalf = blockIdx.y;
    const int tid   = threadIdx.x;

    // token resolution (only khalf==0 needs it)
    if (khalf == 0 && tid < B_) {
        int tok;
        if (t == 0) {
            // detect int64 vs int32 captions: read first 128 bytes (safe for both)
            const int* ci = (const int*)captions;
            bool is64 = true;
            #pragma unroll
            for (int i = 1; i < 32; i += 2) if (ci[i] != 0) is64 = false;
            tok = is64 ? (int)((const long long*)captions)[tid] : ci[tid];
        } else {
            unsigned long long p = g_amax[(t + 1) & 1][tid];  // (t-1)&1 parity
            tok = (int)(0x7FFFFFFFu - (unsigned)(p & 0xFFFFFFFFull));
        }
        stok[tid] = tok;
    }
    // one-time init of argmax accumulators before any K2 runs
    if (t == 0 && blockIdx.x == 0 && blockIdx.y == 0 && tid < 128) {
        g_amax[tid >> 6][tid & 63] = 0ull;
    }

    const float* Wp   = khalf ? W_hh : W_ih;
    const float* hsrc = (t == 0) ? features : g_h[(t + 1) & 1];

    const int r0 = blockIdx.x * 32;
    const int rg = tid >> 4;          // 0..15
    const int bg = tid & 15;          // 0..15
    const int rA = r0 + rg * 2;
    const int b0 = bg * 4;

    float acc[2][4] = {};

    for (int k0 = 0; k0 < 512; k0 += 128) {
        __syncthreads();
        // stage transposed activations: acts[kk][b]
        for (int idx = tid; idx < B_ * 128; idx += 256) {
            int b = idx >> 7, kk = idx & 127;
            float v;
            if (khalf == 0) v = embed[(size_t)stok[b] * E_ + k0 + kk];
            else            v = hsrc[b * H_ + k0 + kk];
            acts[kk][b] = v;
        }
        __syncthreads();

        const float* w0p = Wp + (size_t)rA * 512 + k0;
        const float* w1p = w0p + 512;
        #pragma unroll 4
        for (int kk = 0; kk < 128; kk += 4) {
            float w0[4], w1[4];
            *(float4*)w0 = *(const float4*)(w0p + kk);
            *(float4*)w1 = *(const float4*)(w1p + kk);
            float a[4][4];
            #pragma unroll
            for (int j = 0; j < 4; j++)
                *(float4*)a[j] = *(const float4*)&acts[kk + j][b0];
            #pragma unroll
            for (int j = 0; j < 4; j++)
                #pragma unroll
                for (int bb = 0; bb < 4; bb++) {
                    acc[0][bb] += w0[j] * a[j][bb];
                    acc[1][bb] += w1[j] * a[j][bb];
                }
        }
    }

    float* gp = g_gates[khalf];
    #pragma unroll
    for (int r = 0; r < 2; r++)
        #pragma unroll
        for (int j = 0; j < 4; j++)
            gp[(b0 + j) * G4 + rA + r] = acc[r][j];
}

// =========================================================
// K1b: elementwise LSTM update. grid 128, 256 threads.
// =========================================================
__global__ __launch_bounds__(256) void k_update(
    int t,
    const float* __restrict__ features,
    const float* __restrict__ b_ih,
    const float* __restrict__ b_hh)
{
    int idx = blockIdx.x * 256 + threadIdx.x;   // 0 .. 32767
    int b = idx >> 9, j = idx & 511;
    const float* g0 = &g_gates[0][b * G4];
    const float* g1 = &g_gates[1][b * G4];

    float zi = g0[j]        + g1[j]        + b_ih[j]        + b_hh[j];
    float zf = g0[j + 512]  + g1[j + 512]  + b_ih[j + 512]  + b_hh[j + 512];
    float zg = g0[j + 1024] + g1[j + 1024] + b_ih[j + 1024] + b_hh[j + 1024];
    float zo = g0[j + 1536] + g1[j + 1536] + b_ih[j + 1536] + b_hh[j + 1536];

    float i_ = 1.0f / (1.0f + expf(-zi));
    float f_ = 1.0f / (1.0f + expf(-zf));
    float gg = tanhf(zg);
    float o_ = 1.0f / (1.0f + expf(-zo));

    float c_old = (t == 0) ? features[b * H_ + j] : g_c[b * H_ + j];
    float c_new = f_ * c_old + i_ * gg;
    float h_new = o_ * tanhf(c_new);

    g_c[b * H_ + j]        = c_new;
    g_h[t & 1][b * H_ + j] = h_new;
}

// =========================================================
// K2: vocab projection + argmax. grid 250, 256 threads.
// Block tile: 128 v x 64 b, K=512. Thread tile: 8v x 4b.
// W streamed from L2 (lin_W resident), h staged in smem transposed.
// =========================================================
__global__ __launch_bounds__(256, 2) void k_logits(
    int t,
    const float* __restrict__ lin_W,
    const float* __restrict__ lin_b,
    float* __restrict__ out)
{
    __shared__ float hs[128][68];
    __shared__ unsigned long long s_amax[B_];

    const int tid   = threadIdx.x;
    const int vbase = blockIdx.x * 128;
    const int bg = tid >> 4, vg = tid & 15;
    const int b0 = bg * 4;
    const int vA = vbase + vg * 4;
    const int vB = vA + 64;

    if (tid < B_) s_amax[tid] = 0ull;
    // reset the accumulator the NEXT step's K2 will use (safe: different parity)
    if (blockIdx.x == 0 && tid < B_) g_amax[(t + 1) & 1][tid] = 0ull;

    const float* hsrc = g_h[t & 1];
    float acc[8][4] = {};   // acc[vslot][b]; vslot 0..3 -> vA+., 4..7 -> vB+.

    for (int k0 = 0; k0 < 512; k0 += 128) {
        __syncthreads();
        for (int idx = tid; idx < B_ * 128; idx += 256) {
            int b = idx >> 7, kk = idx & 127;
            hs[kk][b] = hsrc[b * H_ + k0 + kk];
        }
        __syncthreads();

        const float* wA0 = lin_W + (size_t)vA * 512 + k0;
        const float* wB0 = lin_W + (size_t)vB * 512 + k0;
        #pragma unroll 2
        for (int kk = 0; kk < 128; kk += 4) {
            float w[8][4];
            #pragma unroll
            for (int r = 0; r < 4; r++) {
                *(float4*)w[r]     = *(const float4*)(wA0 + (size_t)r * 512 + kk);
                *(float4*)w[r + 4] = *(const float4*)(wB0 + (size_t)r * 512 + kk);
            }
            float a[4][4];
            #pragma unroll
            for (int j = 0; j < 4; j++)
                *(float4*)a[j] = *(const float4*)&hs[kk + j][b0];
            #pragma unroll
            for (int r = 0; r < 8; r++)
                #pragma unroll
                for (int j = 0; j < 4; j++)
                    #pragma unroll
                    for (int bb = 0; bb < 4; bb++)
                        acc[r][bb] += w[r][j] * a[j][bb];
        }
    }

    float bias[8];
    #pragma unroll
    for (int r = 0; r < 4; r++) {
        bias[r]     = lin_b[vA + r];
        bias[r + 4] = lin_b[vB + r];
    }

    #pragma unroll
    for (int bb = 0; bb < 4; bb++) {
        int b = b0 + bb;
        float* orow = out + ((size_t)b * T_ + t) * V_;
        float oA[4], oB[4];
        #pragma unroll
        for (int r = 0; r < 4; r++) {
            oA[r] = acc[r][bb]     + bias[r];
            oB[r] = acc[r + 4][bb] + bias[r + 4];
        }
        *(float4*)(orow + vA) = *(float4*)oA;
        *(float4*)(orow + vB) = *(float4*)oB;

        unsigned long long best = 0ull;
        #pragma unroll
        for (int r = 0; r < 8; r++) {
            int   v   = (r < 4) ? (vA + r) : (vB + r - 4);
            float val = (r < 4) ? oA[r] : oB[r - 4];
            unsigned long long packed =
                ((unsigned long long)fkey(val) << 32) | (unsigned long long)(0x7FFFFFFFu - (unsigned)v);
            if (packed > best) best = packed;
        }
        atomicMax(&s_amax[b], best);
    }
    __syncthreads();
    if (tid < B_) atomicMax(&g_amax[t & 1][tid], s_amax[tid]);
}

// =========================================================
extern "C" void kernel_launch(void* const* d_in, const int* in_sizes, int n_in,
                              void* d_out, int out_size)
{
    const float* features = (const float*)d_in[0];
    const void*  captions = d_in[1];
    // 'lengths' is a python scalar; it may or may not be materialized as input 2.
    int off = (in_sizes[2] == V_ * E_) ? 0 : 1;
    const float* embed = (const float*)d_in[2 + off];
    const float* W_ih  = (const float*)d_in[3 + off];
    const float* W_hh  = (const float*)d_in[4 + off];
    const float* b_ih  = (const float*)d_in[5 + off];
    const float* b_hh  = (const float*)d_in[6 + off];
    const float* lin_W = (const float*)d_in[7 + off];
    const float* lin_b = (const float*)d_in[8 + off];
    float* out = (float*)d_out;
    (void)n_in; (void)out_size;

    for (int t = 0; t < T_; t++) {
        k_gates <<<dim3(64, 2), 256>>>(t, features, captions, embed, W_ih, W_hh);
        k_update<<<128, 256>>>(t, features, b_ih, b_hh);
        k_logits<<<250, 256>>>(t, lin_W, lin_b, out);
    }
}

// round 2
// speedup vs baseline: 2.6588x; 2.6588x over previous
#include <cuda_runtime.h>
#include <cuda_bf16.h>
#include <math.h>
#include <stdint.h>

#define B_  64
#define E_  512
#define H_  512
#define V_  32000
#define T_  32
#define G4  2048   // 4*H

typedef unsigned long long ull;

// ---------------- persistent device state ----------------
__device__ __align__(16) float g_h[2][B_ * H_];     // double-buffered hidden state
__device__ __align__(16) float g_c[B_ * H_];        // cell state
__device__ __align__(16) float g_gates[4][B_ * G4]; // partials: (W_ih k0,W_ih k1,W_hh k0,W_hh k1)
__device__ ull g_amax[2][B_];                       // double-buffered packed argmax

// ordered-float key: monotonic float -> uint32
__device__ __forceinline__ unsigned fkey(float f) {
    unsigned u = __float_as_uint(f);
    return (u & 0x80000000u) ? ~u : (u | 0x80000000u);
}
// pack (x,x) into f32x2
__device__ __forceinline__ ull pk2(float x) {
    ull r; asm("mov.b64 %0, {%1, %1};" : "=l"(r) : "f"(x)); return r;
}
__device__ __forceinline__ void fma2(ull& d, ull a, ull b) {
    asm("fma.rn.f32x2 %0, %1, %2, %0;" : "+l"(d) : "l"(a), "l"(b));
}
__device__ __forceinline__ void unpk(float& lo, float& hi, ull v) {
    asm("mov.b64 {%0, %1}, %2;" : "=f"(lo), "=f"(hi) : "l"(v));
}

// =========================================================
// K1a: gate partials. grid (32, 4), 256 threads.
//   part p: weight = (p<2 ? W_ih : W_hh), act = (p<2 ? embed[tok] : h_prev),
//   k range = (p&1)*256 .. +256.
// Block tile: 64 gate-rows x 64 batch, K=256 (8 chunks of 32).
// Thread: rg=tid>>4, bg=tid&15; rows r = rb + 2*rg + 32*i (i=0..1), b = bg*4..+3.
// =========================================================
__global__ __launch_bounds__(256, 2) void k_gates(
    int t,
    const float* __restrict__ features,
    const void*  __restrict__ captions,
    const float* __restrict__ embed,
    const float* __restrict__ W_ih,
    const float* __restrict__ W_hh)
{
    __shared__ __align__(16) float Ws[32][66];   // [k][r] transposed weight chunk
    __shared__ __align__(16) float as[64][33];   // [b][k] activation chunk
    __shared__ int stok[B_];

    const int tid = threadIdx.x;
    const int p   = blockIdx.y;
    const int wsel = p >> 1;            // 0: W_ih/x   1: W_hh/h
    const int koff = (p & 1) * 256;
    const int rb  = blockIdx.x * 64;

    if (wsel == 0 && tid < B_) {
        int tok;
        if (t == 0) {
            const int* ci = (const int*)captions;
            bool is64 = true;
            #pragma unroll
            for (int i = 1; i < 32; i += 2) if (ci[i] != 0) is64 = false;
            tok = is64 ? (int)((const long long*)captions)[tid] : ci[tid];
        } else {
            ull pk = g_amax[(t + 1) & 1][tid];
            tok = (int)(0x7FFFFFFFu - (unsigned)(pk & 0xFFFFFFFFull));
        }
        stok[tid] = tok;
    }
    if (t == 0 && blockIdx.x == 0 && blockIdx.y == 0 && tid < 128)
        g_amax[tid >> 6][tid & 63] = 0ull;

    const float* Wp   = wsel ? W_hh : W_ih;
    const float* hsrc = (t == 0) ? features : g_h[(t + 1) & 1];

    const int rg = tid >> 4;           // 0..15
    const int bg = tid & 15;           // 0..15
    const int b0 = bg * 4;

    ull acc[4][2] = {};                // [bb][rpair]

    for (int kc = koff; kc < koff + 256; kc += 32) {
        __syncthreads();
        // stage Ws[k][r]  (64r x 32k, transpose)
        #pragma unroll
        for (int q = 0; q < 2; q++) {
            int idx = tid + q * 256;         // 0..511
            int r = idx >> 3, kq = idx & 7;
            float4 w4 = *(const float4*)(Wp + (size_t)(rb + r) * 512 + kc + kq * 4);
            Ws[kq * 4 + 0][r] = w4.x; Ws[kq * 4 + 1][r] = w4.y;
            Ws[kq * 4 + 2][r] = w4.z; Ws[kq * 4 + 3][r] = w4.w;
        }
        // stage as[b][k]
        #pragma unroll
        for (int q = 0; q < 2; q++) {
            int idx = tid + q * 256;
            int b = idx >> 3, kq = idx & 7;
            const float* src = wsel ? (hsrc + b * 512 + kc + kq * 4)
                                    : (embed + (size_t)stok[b] * E_ + kc + kq * 4);
            float4 a4 = *(const float4*)src;
            as[b][kq * 4 + 0] = a4.x; as[b][kq * 4 + 1] = a4.y;
            as[b][kq * 4 + 2] = a4.z; as[b][kq * 4 + 3] = a4.w;
        }
        __syncthreads();

        #pragma unroll 8
        for (int k = 0; k < 32; k++) {
            ull wp0 = *(const ull*)&Ws[k][2 * rg];
            ull wp1 = *(const ull*)&Ws[k][2 * rg + 32];
            #pragma unroll
            for (int bb = 0; bb < 4; bb++) {
                ull ap = pk2(as[b0 + bb][k]);
                fma2(acc[bb][0], wp0, ap);
                fma2(acc[bb][1], wp1, ap);
            }
        }
    }

    float* gp = g_gates[p];
    #pragma unroll
    for (int bb = 0; bb < 4; bb++) {
        #pragma unroll
        for (int i = 0; i < 2; i++) {
            int r = rb + 2 * rg + 32 * i;
            *(ull*)&gp[(b0 + bb) * G4 + r] = acc[bb][i];
        }
    }
}

// =========================================================
// K1b: elementwise LSTM update (sums 4 partials). grid 128, 256 threads.
// =========================================================
__global__ __launch_bounds__(256) void k_update(
    int t,
    const float* __restrict__ features,
    const float* __restrict__ b_ih,
    const float* __restrict__ b_hh)
{
    int idx = blockIdx.x * 256 + threadIdx.x;   // 0 .. 32767
    int b = idx >> 9, j = idx & 511;
    const int base = b * G4;

    float z[4];
    #pragma unroll
    for (int g = 0; g < 4; g++) {
        int o = base + j + g * 512;
        z[g] = g_gates[0][o] + g_gates[1][o] + g_gates[2][o] + g_gates[3][o]
             + b_ih[j + g * 512] + b_hh[j + g * 512];
    }
    float i_ = 1.0f / (1.0f + expf(-z[0]));
    float f_ = 1.0f / (1.0f + expf(-z[1]));
    float gg = tanhf(z[2]);
    float o_ = 1.0f / (1.0f + expf(-z[3]));

    float c_old = (t == 0) ? features[b * H_ + j] : g_c[b * H_ + j];
    float c_new = f_ * c_old + i_ * gg;
    float h_new = o_ * tanhf(c_new);

    g_c[b * H_ + j]        = c_new;
    g_h[t & 1][b * H_ + j] = h_new;
}

// =========================================================
// K2: vocab projection + argmax. grid 250, 256 threads.
// Block tile: 128 v x 64 b, K=512 in 32-k chunks.
// Thread: bg=tid>>4, vg=tid&15; v-pairs v = vbase + 2*vg + 32*i (i=0..3), b = bg*4..+3.
// Weights staged transposed (k-major, v-contig) -> conflict-free LDS.64 pairs,
// f32x2 FMA packing over v.
// =========================================================
__global__ __launch_bounds__(256, 3) void k_logits(
    int t,
    const float* __restrict__ lin_W,
    const float* __restrict__ lin_b,
    float* __restrict__ out)
{
    __shared__ __align__(16) float Ws[32][130];  // [k][v]
    __shared__ __align__(16) float hs[64][33];   // [b][k]
    __shared__ ull s_amax[B_];

    const int tid   = threadIdx.x;
    const int vbase = blockIdx.x * 128;
    const int bg = tid >> 4, vg = tid & 15;
    const int b0 = bg * 4;

    if (tid < B_) s_amax[tid] = 0ull;
    if (blockIdx.x == 0 && tid < B_) g_amax[(t + 1) & 1][tid] = 0ull;

    const float* hsrc = g_h[t & 1];
    ull acc[4][4] = {};                 // [bb][vpair i]

    for (int k0 = 0; k0 < 512; k0 += 32) {
        __syncthreads();
        // stage Ws[k][v] (128v x 32k, transpose; coalesced LDG.128)
        #pragma unroll
        for (int q = 0; q < 4; q++) {
            int idx = tid + q * 256;          // 0..1023
            int v = idx >> 3, kq = idx & 7;
            float4 w4 = *(const float4*)(lin_W + (size_t)(vbase + v) * 512 + k0 + kq * 4);
            Ws[kq * 4 + 0][v] = w4.x; Ws[kq * 4 + 1][v] = w4.y;
            Ws[kq * 4 + 2][v] = w4.z; Ws[kq * 4 + 3][v] = w4.w;
        }
        // stage hs[b][k]
        #pragma unroll
        for (int q = 0; q < 2; q++) {
            int idx = tid + q * 256;
            int b = idx >> 3, kq = idx & 7;
            float4 h4 = *(const float4*)(hsrc + b * 512 + k0 + kq * 4);
            hs[b][kq * 4 + 0] = h4.x; hs[b][kq * 4 + 1] = h4.y;
            hs[b][kq * 4 + 2] = h4.z; hs[b][kq * 4 + 3] = h4.w;
        }
        __syncthreads();

        #pragma unroll 8
        for (int k = 0; k < 32; k++) {
            ull wp0 = *(const ull*)&Ws[k][2 * vg];
            ull wp1 = *(const ull*)&Ws[k][2 * vg + 32];
            ull wp2 = *(const ull*)&Ws[k][2 * vg + 64];
            ull wp3 = *(const ull*)&Ws[k][2 * vg + 96];
            #pragma unroll
            for (int bb = 0; bb < 4; bb++) {
                ull ap = pk2(hs[b0 + bb][k]);
                fma2(acc[bb][0], wp0, ap);
                fma2(acc[bb][1], wp1, ap);
                fma2(acc[bb][2], wp2, ap);
                fma2(acc[bb][3], wp3, ap);
            }
        }
    }

    // epilogue: bias, store, argmax
    float blo[4], bhi[4];
    #pragma unroll
    for (int i = 0; i < 4; i++) {
        int v = vbase + 2 * vg + 32 * i;
        blo[i] = lin_b[v]; bhi[i] = lin_b[v + 1];
    }
    #pragma unroll
    for (int bb = 0; bb < 4; bb++) {
        int b = b0 + bb;
        float* orow = out + ((size_t)b * T_ + t) * V_;
        ull best = 0ull;
        #pragma unroll
        for (int i = 0; i < 4; i++) {
            int v = vbase + 2 * vg + 32 * i;
            float lo, hi; unpk(lo, hi, acc[bb][i]);
            lo += blo[i]; hi += bhi[i];
            float2 st; st.x = lo; st.y = hi;
            *(float2*)(orow + v) = st;
            ull plo = ((ull)fkey(lo) << 32) | (ull)(0x7FFFFFFFu - (unsigned)v);
            ull phi = ((ull)fkey(hi) << 32) | (ull)(0x7FFFFFFFu - (unsigned)(v + 1));
            if (plo > best) best = plo;
            if (phi > best) best = phi;
        }
        atomicMax(&s_amax[b], best);
    }
    __syncthreads();
    if (tid < B_) atomicMax(&g_amax[t & 1][tid], s_amax[tid]);
}

// =========================================================
extern "C" void kernel_launch(void* const* d_in, const int* in_sizes, int n_in,
                              void* d_out, int out_size)
{
    const float* features = (const float*)d_in[0];
    const void*  captions = d_in[1];
    int off = (in_sizes[2] == V_ * E_) ? 0 : 1;   // 'lengths' may be materialized
    const float* embed = (const float*)d_in[2 + off];
    const float* W_ih  = (const float*)d_in[3 + off];
    const float* W_hh  = (const float*)d_in[4 + off];
    const float* b_ih  = (const float*)d_in[5 + off];
    const float* b_hh  = (const float*)d_in[6 + off];
    const float* lin_W = (const float*)d_in[7 + off];
    const float* lin_b = (const float*)d_in[8 + off];
    float* out = (float*)d_out;
    (void)n_in; (void)out_size;

    for (int t = 0; t < T_; t++) {
        k_gates <<<dim3(32, 4), 256>>>(t, features, captions, embed, W_ih, W_hh);
        k_update<<<128, 256>>>(t, features, b_ih, b_hh);
        k_logits<<<250, 256>>>(t, lin_W, lin_b, out);
    }
}

// round 3
// speedup vs baseline: 2.8177x; 1.0597x over previous
#include <cuda_runtime.h>
#include <cuda_bf16.h>
#include <math.h>
#include <stdint.h>

#define B_  64
#define E_  512
#define H_  512
#define V_  32000
#define T_  32
#define G4  2048   // 4*H

typedef unsigned long long ull;

// ---------------- persistent device state ----------------
__device__ __align__(16) float g_h[2][B_ * H_];     // double-buffered hidden state
__device__ __align__(16) float g_c[B_ * H_];        // cell state
__device__ __align__(16) float g_gates[8][B_ * G4]; // partials: plane = wsel*4 + kblk
__device__ ull g_amax[2][B_];                       // double-buffered packed argmax

// ordered-float key: monotonic float -> uint32
__device__ __forceinline__ unsigned fkey(float f) {
    unsigned u = __float_as_uint(f);
    return (u & 0x80000000u) ? ~u : (u | 0x80000000u);
}
__device__ __forceinline__ void fma2(ull& d, ull a, ull b) {
    asm("fma.rn.f32x2 %0, %1, %2, %0;" : "+l"(d) : "l"(a), "l"(b));
}
__device__ __forceinline__ void unpk(float& lo, float& hi, ull v) {
    asm("mov.b64 {%0, %1}, %2;" : "=f"(lo), "=f"(hi) : "l"(v));
}

// =========================================================
// K1a: gate partials. grid (32, 4, 4), 256 threads.
//   x: 64-row block of the 2048 gate rows
//   y: k-block (128 k each)
//   z: wsel*2 + bhalf   (wsel 0: W_ih/x, 1: W_hh/h; bhalf: 32-batch half)
// Partial plane = wsel*4 + kblk. Block tile 64r x 32b x 128k.
// Thread: rg=tid&15 (rpairs r=2rg+32i, i<2), bg=tid>>4 (b=2bg,2bg+1).
// =========================================================
__global__ __launch_bounds__(256) void k_gates(
    int t,
    const float* __restrict__ features,
    const void*  __restrict__ captions,
    const float* __restrict__ embed,
    const float* __restrict__ W_ih,
    const float* __restrict__ W_hh)
{
    __shared__ __align__(16) float Ws[32][66];   // [k][r]
    __shared__ __align__(16) float ad[32][66];   // [k][2b] duplicated activations
    __shared__ int stok[32];

    const int tid  = threadIdx.x;
    const int rb   = blockIdx.x * 64;
    const int kblk = blockIdx.y;
    const int koff = kblk * 128;
    const int wsel = blockIdx.z >> 1;
    const int bh   = blockIdx.z & 1;
    const int b0g  = bh * 32;
    const int plane = wsel * 4 + kblk;

    if (wsel == 0 && tid < 32) {
        int gb = b0g + tid;
        int tok;
        if (t == 0) {
            const int* ci = (const int*)captions;
            bool is64 = true;
            #pragma unroll
            for (int i = 1; i < 32; i += 2) if (ci[i] != 0) is64 = false;
            tok = is64 ? (int)((const long long*)captions)[gb] : ci[gb];
        } else {
            ull pk = g_amax[(t + 1) & 1][gb];
            tok = (int)(0x7FFFFFFFu - (unsigned)(pk & 0xFFFFFFFFull));
        }
        stok[tid] = tok;
    }
    if (t == 0 && blockIdx.x == 0 && blockIdx.y == 0 && blockIdx.z == 0 && tid < 128)
        g_amax[tid >> 6][tid & 63] = 0ull;

    const float* Wp   = wsel ? W_hh : W_ih;
    const float* hsrc = ((t == 0) ? features : g_h[(t + 1) & 1]) + b0g * 512;

    const int rg = tid & 15;
    const int bg = tid >> 4;

    ull acc[2][2] = {};     // [bb][rpair i]

    for (int kc = koff; kc < koff + 128; kc += 32) {
        __syncthreads();
        // stage Ws[k][r]: 64r x 32k
        #pragma unroll
        for (int q = 0; q < 2; q++) {
            int idx = tid + q * 256;
            int r = idx >> 3, kq = idx & 7;
            float4 w4 = *(const float4*)(Wp + (size_t)(rb + r) * 512 + kc + kq * 4);
            Ws[kq * 4 + 0][r] = w4.x; Ws[kq * 4 + 1][r] = w4.y;
            Ws[kq * 4 + 2][r] = w4.z; Ws[kq * 4 + 3][r] = w4.w;
        }
        // stage ad[k][2b] duplicated: 32b x 32k
        {
            int b = tid >> 3, kq = tid & 7;
            const float* src = wsel ? (hsrc + b * 512 + kc + kq * 4)
                                    : (embed + (size_t)stok[b] * E_ + kc + kq * 4);
            float4 a4 = *(const float4*)src;
            float2 d;
            d.x = a4.x; d.y = a4.x; *(float2*)&ad[kq * 4 + 0][2 * b] = d;
            d.x = a4.y; d.y = a4.y; *(float2*)&ad[kq * 4 + 1][2 * b] = d;
            d.x = a4.z; d.y = a4.z; *(float2*)&ad[kq * 4 + 2][2 * b] = d;
            d.x = a4.w; d.y = a4.w; *(float2*)&ad[kq * 4 + 3][2 * b] = d;
        }
        __syncthreads();

        #pragma unroll 8
        for (int k = 0; k < 32; k++) {
            ull w0 = *(const ull*)&Ws[k][2 * rg];
            ull w1 = *(const ull*)&Ws[k][2 * rg + 32];
            ull a0 = *(const ull*)&ad[k][4 * bg];
            ull a1 = *(const ull*)&ad[k][4 * bg + 2];
            fma2(acc[0][0], w0, a0);
            fma2(acc[0][1], w1, a0);
            fma2(acc[1][0], w0, a1);
            fma2(acc[1][1], w1, a1);
        }
    }

    float* gp = g_gates[plane];
    #pragma unroll
    for (int bb = 0; bb < 2; bb++)
        #pragma unroll
        for (int i = 0; i < 2; i++)
            *(ull*)&gp[(size_t)(b0g + 2 * bg + bb) * G4 + rb + 2 * rg + 32 * i] = acc[bb][i];
}

// =========================================================
// K1b: elementwise LSTM update (sums 8 partials). grid 128, 256 threads.
// =========================================================
__global__ __launch_bounds__(256) void k_update(
    int t,
    const float* __restrict__ features,
    const float* __restrict__ b_ih,
    const float* __restrict__ b_hh)
{
    int idx = blockIdx.x * 256 + threadIdx.x;   // 0 .. 32767
    int b = idx >> 9, j = idx & 511;
    const int base = b * G4;

    float z[4];
    #pragma unroll
    for (int g = 0; g < 4; g++) {
        int o = base + j + g * 512;
        float s = b_ih[j + g * 512] + b_hh[j + g * 512];
        #pragma unroll
        for (int p = 0; p < 8; p++) s += g_gates[p][o];
        z[g] = s;
    }
    float i_ = 1.0f / (1.0f + expf(-z[0]));
    float f_ = 1.0f / (1.0f + expf(-z[1]));
    float gg = tanhf(z[2]);
    float o_ = 1.0f / (1.0f + expf(-z[3]));

    float c_old = (t == 0) ? features[b * H_ + j] : g_c[b * H_ + j];
    float c_new = f_ * c_old + i_ * gg;
    float h_new = o_ * tanhf(c_new);

    g_c[b * H_ + j]        = c_new;
    g_h[t & 1][b * H_ + j] = h_new;
}

// =========================================================
// K2: vocab projection + argmax. grid (250, 2), 256 threads.
//   x: 128-v block, y: 32-batch half.
// Thread: vg=tid&15 (vpairs v=2vg+32i, i<4), bg=tid>>4 (b=2bg,2bg+1 local).
// Per-k inner: 4 LDS.64 (W) + 2 LDS.64 (dup act) + 8 FFMA2.
// =========================================================
__global__ __launch_bounds__(256, 3) void k_logits(
    int t,
    const float* __restrict__ lin_W,
    const float* __restrict__ lin_b,
    float* __restrict__ out)
{
    __shared__ __align__(16) float Ws[32][130];  // [k][v]
    __shared__ __align__(16) float hd[32][66];   // [k][2b] duplicated h
    __shared__ ull s_amax[32];

    const int tid   = threadIdx.x;
    const int vbase = blockIdx.x * 128;
    const int b0g   = blockIdx.y * 32;
    const int vg = tid & 15, bg = tid >> 4;

    if (tid < 32) s_amax[tid] = 0ull;
    if (blockIdx.x == 0 && tid < 32) g_amax[(t + 1) & 1][b0g + tid] = 0ull;

    const float* hsrc = g_h[t & 1] + b0g * 512;
    ull acc[2][4] = {};                 // [bb][vpair i]

    for (int k0 = 0; k0 < 512; k0 += 32) {
        __syncthreads();
        // stage Ws[k][v]: 128v x 32k (coalesced LDG.128)
        #pragma unroll
        for (int q = 0; q < 4; q++) {
            int idx = tid + q * 256;
            int v = idx >> 3, kq = idx & 7;
            float4 w4 = *(const float4*)(lin_W + (size_t)(vbase + v) * 512 + k0 + kq * 4);
            Ws[kq * 4 + 0][v] = w4.x; Ws[kq * 4 + 1][v] = w4.y;
            Ws[kq * 4 + 2][v] = w4.z; Ws[kq * 4 + 3][v] = w4.w;
        }
        // stage hd[k][2b] duplicated: 32b x 32k
        {
            int b = tid >> 3, kq = tid & 7;
            float4 h4 = *(const float4*)(hsrc + b * 512 + k0 + kq * 4);
            float2 d;
            d.x = h4.x; d.y = h4.x; *(float2*)&hd[kq * 4 + 0][2 * b] = d;
            d.x = h4.y; d.y = h4.y; *(float2*)&hd[kq * 4 + 1][2 * b] = d;
            d.x = h4.z; d.y = h4.z; *(float2*)&hd[kq * 4 + 2][2 * b] = d;
            d.x = h4.w; d.y = h4.w; *(float2*)&hd[kq * 4 + 3][2 * b] = d;
        }
        __syncthreads();

        #pragma unroll 8
        for (int k = 0; k < 32; k++) {
            ull w0 = *(const ull*)&Ws[k][2 * vg];
            ull w1 = *(const ull*)&Ws[k][2 * vg + 32];
            ull w2 = *(const ull*)&Ws[k][2 * vg + 64];
            ull w3 = *(const ull*)&Ws[k][2 * vg + 96];
            ull a0 = *(const ull*)&hd[k][4 * bg];
            ull a1 = *(const ull*)&hd[k][4 * bg + 2];
            fma2(acc[0][0], w0, a0);
            fma2(acc[0][1], w1, a0);
            fma2(acc[0][2], w2, a0);
            fma2(acc[0][3], w3, a0);
            fma2(acc[1][0], w0, a1);
            fma2(acc[1][1], w1, a1);
            fma2(acc[1][2], w2, a1);
            fma2(acc[1][3], w3, a1);
        }
    }

    // epilogue: bias, store, argmax
    float blo[4], bhi[4];
    #pragma unroll
    for (int i = 0; i < 4; i++) {
        int v = vbase + 2 * vg + 32 * i;
        blo[i] = lin_b[v]; bhi[i] = lin_b[v + 1];
    }
    #pragma unroll
    for (int bb = 0; bb < 2; bb++) {
        int b = b0g + 2 * bg + bb;
        float* orow = out + ((size_t)b * T_ + t) * V_;
        ull best = 0ull;
        #pragma unroll
        for (int i = 0; i < 4; i++) {
            int v = vbase + 2 * vg + 32 * i;
            float lo, hi; unpk(lo, hi, acc[bb][i]);
            lo += blo[i]; hi += bhi[i];
            float2 st; st.x = lo; st.y = hi;
            *(float2*)(orow + v) = st;
            ull plo = ((ull)fkey(lo) << 32) | (ull)(0x7FFFFFFFu - (unsigned)v);
            ull phi = ((ull)fkey(hi) << 32) | (ull)(0x7FFFFFFFu - (unsigned)(v + 1));
            if (plo > best) best = plo;
            if (phi > best) best = phi;
        }
        atomicMax(&s_amax[b - b0g], best);
    }
    __syncthreads();
    if (tid < 32) atomicMax(&g_amax[t & 1][b0g + tid], s_amax[tid]);
}

// =========================================================
extern "C" void kernel_launch(void* const* d_in, const int* in_sizes, int n_in,
                              void* d_out, int out_size)
{
    const float* features = (const float*)d_in[0];
    const void*  captions = d_in[1];
    int off = (in_sizes[2] == V_ * E_) ? 0 : 1;   // 'lengths' may be materialized
    const float* embed = (const float*)d_in[2 + off];
    const float* W_ih  = (const float*)d_in[3 + off];
    const float* W_hh  = (const float*)d_in[4 + off];
    const float* b_ih  = (const float*)d_in[5 + off];
    const float* b_hh  = (const float*)d_in[6 + off];
    const float* lin_W = (const float*)d_in[7 + off];
    const float* lin_b = (const float*)d_in[8 + off];
    float* out = (float*)d_out;
    (void)n_in; (void)out_size;

    for (int t = 0; t < T_; t++) {
        k_gates <<<dim3(32, 4, 4), 256>>>(t, features, captions, embed, W_ih, W_hh);
        k_update<<<128, 256>>>(t, features, b_ih, b_hh);
        k_logits<<<dim3(250, 2), 256>>>(t, lin_W, lin_b, out);
    }
}

// round 5
// speedup vs baseline: 4.5339x; 1.6091x over previous
#include <cuda_runtime.h>
#include <math.h>
#include <stdint.h>

#define B_  64
#define E_  512
#define H_  512
#define V_  32000
#define T_  32
#define G4  2048   // 4*H

typedef unsigned long long ull;

// ---------------- persistent device state ----------------
__device__ __align__(16) float g_h[2][B_ * H_];     // double-buffered hidden state
__device__ __align__(16) float g_c[B_ * H_];        // cell state
__device__ __align__(16) float g_gates[8][B_ * G4]; // planes 0-3: ih k-split, 4-7: hh k-split
__device__ ull g_amax[2][B_];                       // packed argmax accumulators
// k-major (transposed) weight copies
__device__ __align__(16) float g_Wt  [512 * 32000];
__device__ __align__(16) float g_WihT[512 * 2048];
__device__ __align__(16) float g_WhhT[512 * 2048];

__device__ __forceinline__ unsigned fkey(float f) {
    unsigned u = __float_as_uint(f);
    return (u & 0x80000000u) ? ~u : (u | 0x80000000u);
}
__device__ __forceinline__ ull pk2(float x) {
    ull r; asm("mov.b64 %0, {%1, %1};" : "=l"(r) : "f"(x)); return r;
}
__device__ __forceinline__ void fma2(ull& d, ull a, ull b) {
    asm("fma.rn.f32x2 %0, %1, %2, %0;" : "+l"(d) : "l"(a), "l"(b));
}
__device__ __forceinline__ void unpk(float& lo, float& hi, ull v) {
    asm("mov.b64 {%0, %1}, %2;" : "=f"(lo), "=f"(hi) : "l"(v));
}

// =========================================================
// kT: transpose src[R][512] -> dst[512][R]. grid (R/32, 16), block (32,8).
// =========================================================
__global__ __launch_bounds__(256) void kT(const float* __restrict__ src, int which, int R)
{
    __shared__ float tile[32][33];
    float* dst = (which == 0) ? g_Wt : (which == 1) ? g_WihT : g_WhhT;
    const int r0 = blockIdx.x * 32, c0 = blockIdx.y * 32;
    const int tx = threadIdx.x, ty = threadIdx.y;
    #pragma unroll
    for (int i = 0; i < 4; i++)
        tile[ty + 8 * i][tx] = src[(size_t)(r0 + ty + 8 * i) * 512 + c0 + tx];
    __syncthreads();
    #pragma unroll
    for (int i = 0; i < 4; i++)
        dst[(size_t)(c0 + ty + 8 * i) * R + r0 + tx] = tile[tx][ty + 8 * i];
}

// =========================================================
// k_ih: W_ih @ embed[tok] partials -> planes 0-3. grid (32,4,2), 256 thr.
//  x: 64-row block, y: k-block(128), z: 32-batch half.
// Thread: rg=tid&15 (r-quad 4rg), bg=tid>>4 (b=2bg,2bg+1).
// =========================================================
__global__ __launch_bounds__(256) void k_ih(
    int t, const void* __restrict__ captions, const float* __restrict__ embed)
{
    __shared__ __align__(16) float Ws[16][68];
    __shared__ __align__(16) float as_[16][36];
    __shared__ int stok[32];

    const int tid  = threadIdx.x;
    const int r0   = blockIdx.x * 64;
    const int koff = blockIdx.y * 128;
    const int b0g  = blockIdx.z * 32;

    if (tid < 32) {
        int gb = b0g + tid, tok;
        if (t == 0) {
            const int* ci = (const int*)captions;
            bool is64 = true;
            #pragma unroll
            for (int i = 1; i < 32; i += 2) if (ci[i]) is64 = false;
            tok = is64 ? (int)((const long long*)captions)[gb] : ci[gb];
        } else {
            ull pk = g_amax[(t + 1) & 1][gb];
            tok = (int)(0x7FFFFFFFu - (unsigned)(pk & 0xFFFFFFFFull));
        }
        stok[tid] = tok;
    }
    if (t == 0 && blockIdx.x == 0 && blockIdx.y == 0 && blockIdx.z == 0 && tid < 128)
        g_amax[tid >> 6][tid & 63] = 0ull;
    __syncthreads();

    const int rg = tid & 15, bg = tid >> 4;
    const int wk = tid >> 4, wr = tid & 15;   // weight stage: k, r-quad
    const int ab = tid >> 2, akq = tid & 3;   // act stage (tid<128): b, k-quad
    ull acc[2][2] = {};

    float4 wreg, areg;
    wreg = *(const float4*)&g_WihT[(size_t)(koff + wk) * G4 + r0 + wr * 4];
    if (tid < 128) areg = *(const float4*)&embed[(size_t)stok[ab] * E_ + koff + akq * 4];

    for (int c = 0; c < 8; c++) {
        *(float4*)&Ws[wk][wr * 4] = wreg;
        if (tid < 128) {
            as_[akq * 4 + 0][ab] = areg.x; as_[akq * 4 + 1][ab] = areg.y;
            as_[akq * 4 + 2][ab] = areg.z; as_[akq * 4 + 3][ab] = areg.w;
        }
        __syncthreads();
        if (c < 7) {
            int kb = koff + (c + 1) * 16;
            wreg = *(const float4*)&g_WihT[(size_t)(kb + wk) * G4 + r0 + wr * 4];
            if (tid < 128) areg = *(const float4*)&embed[(size_t)stok[ab] * E_ + kb + akq * 4];
        }
        #pragma unroll
        for (int k = 0; k < 16; k++) {
            ulonglong2 W0 = *(const ulonglong2*)&Ws[k][4 * rg];
            float2 hv = *(const float2*)&as_[k][2 * bg];
            ull a0 = pk2(hv.x), a1 = pk2(hv.y);
            fma2(acc[0][0], W0.x, a0); fma2(acc[0][1], W0.y, a0);
            fma2(acc[1][0], W0.x, a1); fma2(acc[1][1], W0.y, a1);
        }
        __syncthreads();
    }
    float* gp = g_gates[blockIdx.y];
    #pragma unroll
    for (int bb = 0; bb < 2; bb++) {
        ulonglong2 o; o.x = acc[bb][0]; o.y = acc[bb][1];
        *(ulonglong2*)&gp[(size_t)(b0g + 2 * bg + bb) * G4 + r0 + 4 * rg] = o;
    }
}

// =========================================================
// k_update: sum 8 partial planes + biases, LSTM nonlinearity. grid 128, 256 thr.
// =========================================================
__global__ __launch_bounds__(256) void k_update(
    int t, const float* __restrict__ features,
    const float* __restrict__ b_ih, const float* __restrict__ b_hh)
{
    int idx = blockIdx.x * 256 + threadIdx.x;
    int b = idx >> 9, j = idx & 511;
    const int base = b * G4;

    float z[4];
    #pragma unroll
    for (int g = 0; g < 4; g++) {
        int o = base + j + g * 512;
        float s = b_ih[j + g * 512] + b_hh[j + g * 512];
        #pragma unroll
        for (int p = 0; p < 8; p++) s += g_gates[p][o];
        z[g] = s;
    }
    float i_ = 1.0f / (1.0f + expf(-z[0]));
    float f_ = 1.0f / (1.0f + expf(-z[1]));
    float gg = tanhf(z[2]);
    float o_ = 1.0f / (1.0f + expf(-z[3]));

    float c_old = (t == 0) ? features[b * H_ + j] : g_c[b * H_ + j];
    float c_new = f_ * c_old + i_ * gg;
    float h_new = o_ * tanhf(c_new);

    g_c[b * H_ + j]        = c_new;
    g_h[t & 1][b * H_ + j] = h_new;
}

// =========================================================
// k_big: bids 0..124 = logits(t) [256v x 64b], bids 125..188 = hh gates for t+1
//        [128r x 64b x 128k -> planes 4-7]. t<0: all bids are hh gates from features.
// =========================================================
__global__ __launch_bounds__(256) void k_big(
    int t, const float* __restrict__ features,
    const float* __restrict__ lin_b, float* __restrict__ out)
{
    __shared__ __align__(16) float Ws[16][260];
    __shared__ __align__(16) float hs[16][68];
    __shared__ ull s_amax[64];

    const int tid = threadIdx.x;
    const int bid = blockIdx.x;
    const bool is_gates = (t < 0) || (bid >= 125);
    const float* hsrc = (t < 0) ? features : g_h[t & 1];

    if (is_gates) {
        const int gid  = (t < 0) ? bid : bid - 125;   // 0..63
        const int r0   = (gid >> 2) * 128;
        const int koff = (gid & 3) * 128;
        float* gp = g_gates[4 + (gid & 3)];
        const int rg = tid & 15, bg = tid >> 4;
        const int wk = tid >> 5, wr = tid & 31;
        const int ab = tid >> 2, akq = tid & 3;
        ull acc[4][4] = {};

        float4 wreg[2], areg;
        #pragma unroll
        for (int q = 0; q < 2; q++)
            wreg[q] = *(const float4*)&g_WhhT[(size_t)(koff + wk + q * 8) * G4 + r0 + wr * 4];
        areg = *(const float4*)&hsrc[ab * 512 + koff + akq * 4];

        for (int c = 0; c < 8; c++) {
            #pragma unroll
            for (int q = 0; q < 2; q++) *(float4*)&Ws[wk + q * 8][wr * 4] = wreg[q];
            hs[akq * 4 + 0][ab] = areg.x; hs[akq * 4 + 1][ab] = areg.y;
            hs[akq * 4 + 2][ab] = areg.z; hs[akq * 4 + 3][ab] = areg.w;
            __syncthreads();
            if (c < 7) {
                int kb = koff + (c + 1) * 16;
                #pragma unroll
                for (int q = 0; q < 2; q++)
                    wreg[q] = *(const float4*)&g_WhhT[(size_t)(kb + wk + q * 8) * G4 + r0 + wr * 4];
                areg = *(const float4*)&hsrc[ab * 512 + kb + akq * 4];
            }
            #pragma unroll
            for (int k = 0; k < 16; k++) {
                ulonglong2 W0 = *(const ulonglong2*)&Ws[k][4 * rg];
                ulonglong2 W1 = *(const ulonglong2*)&Ws[k][4 * rg + 64];
                float4 hv = *(const float4*)&hs[k][4 * bg];
                ull a0 = pk2(hv.x), a1 = pk2(hv.y), a2 = pk2(hv.z), a3 = pk2(hv.w);
                fma2(acc[0][0], W0.x, a0); fma2(acc[0][1], W0.y, a0);
                fma2(acc[0][2], W1.x, a0); fma2(acc[0][3], W1.y, a0);
                fma2(acc[1][0], W0.x, a1); fma2(acc[1][1], W0.y, a1);
                fma2(acc[1][2], W1.x, a1); fma2(acc[1][3], W1.y, a1);
                fma2(acc[2][0], W0.x, a2); fma2(acc[2][1], W0.y, a2);
                fma2(acc[2][2], W1.x, a2); fma2(acc[2][3], W1.y, a2);
                fma2(acc[3][0], W0.x, a3); fma2(acc[3][1], W0.y, a3);
                fma2(acc[3][2], W1.x, a3); fma2(acc[3][3], W1.y, a3);
            }
            __syncthreads();
        }
        #pragma unroll
        for (int bb = 0; bb < 4; bb++) {
            int b = 4 * bg + bb;
            ulonglong2 o0, o1;
            o0.x = acc[bb][0]; o0.y = acc[bb][1];
            o1.x = acc[bb][2]; o1.y = acc[bb][3];
            *(ulonglong2*)&gp[(size_t)b * G4 + r0 + 4 * rg]      = o0;
            *(ulonglong2*)&gp[(size_t)b * G4 + r0 + 4 * rg + 64] = o1;
        }
        return;
    }

    // -------- logits path: 256v x 64b x 512k --------
    const int vb = bid * 256;
    const int vg = tid & 15, bg = tid >> 4;
    if (tid < 64) s_amax[tid] = 0ull;
    if (bid == 0 && tid < 64) g_amax[(t + 1) & 1][tid] = 0ull;

    const int wk = tid >> 6, wvq = tid & 63;   // stage: k = wk + q*4, v-quad
    const int ab = tid >> 2, akq = tid & 3;
    ull acc[4][8] = {};

    float4 wreg[4], areg;
    #pragma unroll
    for (int q = 0; q < 4; q++)
        wreg[q] = *(const float4*)&g_Wt[(size_t)(wk + q * 4) * V_ + vb + wvq * 4];
    areg = *(const float4*)&hsrc[ab * 512 + akq * 4];

    for (int c = 0; c < 32; c++) {
        #pragma unroll
        for (int q = 0; q < 4; q++) *(float4*)&Ws[wk + q * 4][wvq * 4] = wreg[q];
        hs[akq * 4 + 0][ab] = areg.x; hs[akq * 4 + 1][ab] = areg.y;
        hs[akq * 4 + 2][ab] = areg.z; hs[akq * 4 + 3][ab] = areg.w;
        __syncthreads();
        if (c < 31) {
            int kb = (c + 1) * 16;
            #pragma unroll
            for (int q = 0; q < 4; q++)
                wreg[q] = *(const float4*)&g_Wt[(size_t)(kb + wk + q * 4) * V_ + vb + wvq * 4];
            areg = *(const float4*)&hsrc[ab * 512 + kb + akq * 4];
        }
        #pragma unroll
        for (int k = 0; k < 16; k++) {
            ulonglong2 W0 = *(const ulonglong2*)&Ws[k][4 * vg];
            ulonglong2 W1 = *(const ulonglong2*)&Ws[k][4 * vg + 64];
            ulonglong2 W2 = *(const ulonglong2*)&Ws[k][4 * vg + 128];
            ulonglong2 W3 = *(const ulonglong2*)&Ws[k][4 * vg + 192];
            float4 hv = *(const float4*)&hs[k][4 * bg];
            ull a0 = pk2(hv.x), a1 = pk2(hv.y), a2 = pk2(hv.z), a3 = pk2(hv.w);
            fma2(acc[0][0], W0.x, a0); fma2(acc[0][1], W0.y, a0);
            fma2(acc[0][2], W1.x, a0); fma2(acc[0][3], W1.y, a0);
            fma2(acc[0][4], W2.x, a0); fma2(acc[0][5], W2.y, a0);
            fma2(acc[0][6], W3.x, a0); fma2(acc[0][7], W3.y, a0);
            fma2(acc[1][0], W0.x, a1); fma2(acc[1][1], W0.y, a1);
            fma2(acc[1][2], W1.x, a1); fma2(acc[1][3], W1.y, a1);
            fma2(acc[1][4], W2.x, a1); fma2(acc[1][5], W2.y, a1);
            fma2(acc[1][6], W3.x, a1); fma2(acc[1][7], W3.y, a1);
            fma2(acc[2][0], W0.x, a2); fma2(acc[2][1], W0.y, a2);
            fma2(acc[2][2], W1.x, a2); fma2(acc[2][3], W1.y, a2);
            fma2(acc[2][4], W2.x, a2); fma2(acc[2][5], W2.y, a2);
            fma2(acc[2][6], W3.x, a2); fma2(acc[2][7], W3.y, a2);
            fma2(acc[3][0], W0.x, a3); fma2(acc[3][1], W0.y, a3);
            fma2(acc[3][2], W1.x, a3); fma2(acc[3][3], W1.y, a3);
            fma2(acc[3][4], W2.x, a3); fma2(acc[3][5], W2.y, a3);
            fma2(acc[3][6], W3.x, a3); fma2(acc[3][7], W3.y, a3);
        }
        __syncthreads();
    }

    #pragma unroll
    for (int bb = 0; bb < 4; bb++) {
        int b = 4 * bg + bb;
        float* orow = out + ((size_t)b * T_ + t) * V_;
        ull best = 0ull;
        #pragma unroll
        for (int i = 0; i < 4; i++) {
            int v0 = vb + 4 * vg + 64 * i;
            float4 bi = *(const float4*)&lin_b[v0];
            float l0, h0, l1, h1;
            unpk(l0, h0, acc[bb][2 * i]);
            unpk(l1, h1, acc[bb][2 * i + 1]);
            float4 st;
            st.x = l0 + bi.x; st.y = h0 + bi.y; st.z = l1 + bi.z; st.w = h1 + bi.w;
            *(float4*)&orow[v0] = st;
            ull p;
            p = ((ull)fkey(st.x) << 32) | (ull)(0x7FFFFFFFu - (unsigned)(v0));     if (p > best) best = p;
            p = ((ull)fkey(st.y) << 32) | (ull)(0x7FFFFFFFu - (unsigned)(v0 + 1)); if (p > best) best = p;
            p = ((ull)fkey(st.z) << 32) | (ull)(0x7FFFFFFFu - (unsigned)(v0 + 2)); if (p > best) best = p;
            p = ((ull)fkey(st.w) << 32) | (ull)(0x7FFFFFFFu - (unsigned)(v0 + 3)); if (p > best) best = p;
        }
        atomicMax(&s_amax[b], best);
    }
    __syncthreads();
    if (tid < 64) atomicMax(&g_amax[t & 1][tid], s_amax[tid]);
}

// =========================================================
extern "C" void kernel_launch(void* const* d_in, const int* in_sizes, int n_in,
                              void* d_out, int out_size)
{
    const float* features = (const float*)d_in[0];
    const void*  captions = d_in[1];
    int off = (in_sizes[2] == V_ * E_) ? 0 : 1;   // 'lengths' may be materialized
    const float* embed = (const float*)d_in[2 + off];
    const float* W_ih  = (const float*)d_in[3 + off];
    const float* W_hh  = (const float*)d_in[4 + off];
    const float* b_ih  = (const float*)d_in[5 + off];
    const float* b_hh  = (const float*)d_in[6 + off];
    const float* lin_W = (const float*)d_in[7 + off];
    const float* lin_b = (const float*)d_in[8 + off];
    float* out = (float*)d_out;
    (void)n_in; (void)out_size; (void)embed;

    // one-time-per-launch weight transposes (k-major)
    kT<<<dim3(1000, 16), dim3(32, 8)>>>(lin_W, 0, 32000);
    kT<<<dim3(64, 16),  dim3(32, 8)>>>(W_ih, 1, 2048);
    kT<<<dim3(64, 16),  dim3(32, 8)>>>(W_hh, 2, 2048);

    // pre-compute hh planes for t=0 from features (h(-1) = features)
    k_big<<<64, 256>>>(-1, features, lin_b, out);

    for (int t = 0; t < T_; t++) {
        k_ih<<<dim3(32, 4, 2), 256>>>(t, captions, embed);
        k_update<<<128, 256>>>(t, features, b_ih, b_hh);
        k_big<<<189, 256>>>(t, features, lin_b, out);
    }
}

// round 7
// speedup vs baseline: 7.2579x; 1.6008x over previous
#include <cuda_runtime.h>
#include <cuda_bf16.h>
#include <math.h>
#include <stdint.h>

#define B_  64
#define E_  512
#define H_  512
#define V_  32000
#define T_  32
#define G4  2048   // 4*H

typedef unsigned long long ull;

// ---------------- persistent device state ----------------
__device__ __align__(16) float g_h[2][B_ * H_];     // double-buffered hidden state
__device__ __align__(16) float g_c[B_ * H_];        // cell state
__device__ __align__(16) float g_gates[8][B_ * G4]; // planes 0-3: ih k-split, 4-7: hh k-split
__device__ ull g_amax[2][B_];                       // packed argmax accumulators
__device__ __align__(16) float g_WihT[512 * 2048];  // k-major
__device__ __align__(16) float g_WhhT[512 * 2048];  // k-major
// bf16 2-term splits of lin_W (v-major) and of h(t)
__device__ __align__(16) __nv_bfloat16 g_Wb1[(size_t)V_ * 512];
__device__ __align__(16) __nv_bfloat16 g_Wb2[(size_t)V_ * 512];
__device__ __align__(16) __nv_bfloat16 g_hb[2][B_ * 512];   // [term][b*512+k]

__device__ __forceinline__ unsigned fkey(float f) {
    unsigned u = __float_as_uint(f);
    return (u & 0x80000000u) ? ~u : (u | 0x80000000u);
}
__device__ __forceinline__ ull pk2(float x) {
    ull r; asm("mov.b64 %0, {%1, %1};" : "=l"(r) : "f"(x)); return r;
}
__device__ __forceinline__ void fma2(ull& d, ull a, ull b) {
    asm("fma.rn.f32x2 %0, %1, %2, %0;" : "+l"(d) : "l"(a), "l"(b));
}
__device__ __forceinline__ uint32_t smem_u32(const void* p) {
    uint32_t a;
    asm("{ .reg .u64 t; cvta.to.shared.u64 t, %1; cvt.u32.u64 %0, t; }" : "=r"(a) : "l"(p));
    return a;
}
__device__ __forceinline__ void ldsm4(uint32_t* r, uint32_t addr) {
    asm volatile("ldmatrix.sync.aligned.m8n8.x4.shared.b16 {%0,%1,%2,%3}, [%4];"
        : "=r"(r[0]), "=r"(r[1]), "=r"(r[2]), "=r"(r[3]) : "r"(addr));
}
__device__ __forceinline__ void mma16816(float* d, const uint32_t* a, uint32_t b0, uint32_t b1) {
    asm volatile("mma.sync.aligned.m16n8k16.row.col.f32.bf16.bf16.f32 "
        "{%0,%1,%2,%3}, {%4,%5,%6,%7}, {%8,%9}, {%0,%1,%2,%3};"
        : "+f"(d[0]), "+f"(d[1]), "+f"(d[2]), "+f"(d[3])
        : "r"(a[0]), "r"(a[1]), "r"(a[2]), "r"(a[3]), "r"(b0), "r"(b1));
}
__device__ __forceinline__ void cpasync16(uint32_t dst, const void* src) {
    asm volatile("cp.async.cg.shared.global [%0], [%1], 16;" :: "r"(dst), "l"(src));
}
#define SW128(o) ((o) ^ (((o) >> 3) & 0x70))

// =========================================================
// kT: transpose src[R][512] -> dst[512][R]. grid (R/32, 16), block (32,8).
// =========================================================
__global__ __launch_bounds__(256) void kT(const float* __restrict__ src, int which, int R)
{
    __shared__ float tile[32][33];
    float* dst = (which == 1) ? g_WihT : g_WhhT;
    const int r0 = blockIdx.x * 32, c0 = blockIdx.y * 32;
    const int tx = threadIdx.x, ty = threadIdx.y;
    #pragma unroll
    for (int i = 0; i < 4; i++)
        tile[ty + 8 * i][tx] = src[(size_t)(r0 + ty + 8 * i) * 512 + c0 + tx];
    __syncthreads();
    #pragma unroll
    for (int i = 0; i < 4; i++)
        dst[(size_t)(c0 + ty + 8 * i) * R + r0 + tx] = tile[tx][ty + 8 * i];
}

// =========================================================
// k_split: lin_W -> bf16 hi/lo terms. grid 64000, 256 thr.
// =========================================================
__global__ __launch_bounds__(256) void k_split(const float* __restrict__ W)
{
    size_t i = (size_t)blockIdx.x * 256 + threadIdx.x;
    if (i < (size_t)V_ * 512) {
        float w = W[i];
        __nv_bfloat16 h1 = __float2bfloat16(w);
        g_Wb1[i] = h1;
        g_Wb2[i] = __float2bfloat16(w - __bfloat162float(h1));
    }
}

// =========================================================
// k_ih: W_ih @ embed[tok] partials -> planes 0-3. grid (32,4,2), 256 thr.
// =========================================================
__global__ __launch_bounds__(256) void k_ih(
    int t, const void* __restrict__ captions, const float* __restrict__ embed)
{
    __shared__ __align__(16) float Ws[16][68];
    __shared__ __align__(16) float as_[16][36];
    __shared__ int stok[32];

    const int tid  = threadIdx.x;
    const int r0   = blockIdx.x * 64;
    const int koff = blockIdx.y * 128;
    const int b0g  = blockIdx.z * 32;

    if (tid < 32) {
        int gb = b0g + tid, tok;
        if (t == 0) {
            const int* ci = (const int*)captions;
            bool is64 = true;
            #pragma unroll
            for (int i = 1; i < 32; i += 2) if (ci[i]) is64 = false;
            tok = is64 ? (int)((const long long*)captions)[gb] : ci[gb];
        } else {
            ull pk = g_amax[(t + 1) & 1][gb];
            tok = (int)(0x7FFFFFFFu - (unsigned)(pk & 0xFFFFFFFFull));
        }
        stok[tid] = tok;
    }
    if (t == 0 && blockIdx.x == 0 && blockIdx.y == 0 && blockIdx.z == 0 && tid < 128)
        g_amax[tid >> 6][tid & 63] = 0ull;
    __syncthreads();

    const int rg = tid & 15, bg = tid >> 4;
    const int wk = tid >> 4, wr = tid & 15;
    const int ab = tid >> 2, akq = tid & 3;
    ull acc[2][2] = {};

    float4 wreg, areg;
    wreg = *(const float4*)&g_WihT[(size_t)(koff + wk) * G4 + r0 + wr * 4];
    if (tid < 128) areg = *(const float4*)&embed[(size_t)stok[ab] * E_ + koff + akq * 4];

    for (int c = 0; c < 8; c++) {
        *(float4*)&Ws[wk][wr * 4] = wreg;
        if (tid < 128) {
            as_[akq * 4 + 0][ab] = areg.x; as_[akq * 4 + 1][ab] = areg.y;
            as_[akq * 4 + 2][ab] = areg.z; as_[akq * 4 + 3][ab] = areg.w;
        }
        __syncthreads();
        if (c < 7) {
            int kb = koff + (c + 1) * 16;
            wreg = *(const float4*)&g_WihT[(size_t)(kb + wk) * G4 + r0 + wr * 4];
            if (tid < 128) areg = *(const float4*)&embed[(size_t)stok[ab] * E_ + kb + akq * 4];
        }
        #pragma unroll
        for (int k = 0; k < 16; k++) {
            ulonglong2 W0 = *(const ulonglong2*)&Ws[k][4 * rg];
            float2 hv = *(const float2*)&as_[k][2 * bg];
            ull a0 = pk2(hv.x), a1 = pk2(hv.y);
            fma2(acc[0][0], W0.x, a0); fma2(acc[0][1], W0.y, a0);
            fma2(acc[1][0], W0.x, a1); fma2(acc[1][1], W0.y, a1);
        }
        __syncthreads();
    }
    float* gp = g_gates[blockIdx.y];
    #pragma unroll
    for (int bb = 0; bb < 2; bb++) {
        ulonglong2 o; o.x = acc[bb][0]; o.y = acc[bb][1];
        *(ulonglong2*)&gp[(size_t)(b0g + 2 * bg + bb) * G4 + r0 + 4 * rg] = o;
    }
}

// =========================================================
// k_update: sum 8 planes + biases, LSTM nonlin, write h + bf16 splits.
// =========================================================
__global__ __launch_bounds__(256) void k_update(
    int t, const float* __restrict__ features,
    const float* __restrict__ b_ih, const float* __restrict__ b_hh)
{
    int idx = blockIdx.x * 256 + threadIdx.x;
    int b = idx >> 9, j = idx & 511;
    const int base = b * G4;

    float z[4];
    #pragma unroll
    for (int g = 0; g < 4; g++) {
        int o = base + j + g * 512;
        float s = b_ih[j + g * 512] + b_hh[j + g * 512];
        #pragma unroll
        for (int p = 0; p < 8; p++) s += g_gates[p][o];
        z[g] = s;
    }
    float i_ = 1.0f / (1.0f + expf(-z[0]));
    float f_ = 1.0f / (1.0f + expf(-z[1]));
    float gg = tanhf(z[2]);
    float o_ = 1.0f / (1.0f + expf(-z[3]));

    float c_old = (t == 0) ? features[b * H_ + j] : g_c[b * H_ + j];
    float c_new = f_ * c_old + i_ * gg;
    float h_new = o_ * tanhf(c_new);

    g_c[b * H_ + j]        = c_new;
    g_h[t & 1][b * H_ + j] = h_new;

    __nv_bfloat16 h1 = __float2bfloat16(h_new);
    g_hb[0][b * 512 + j] = h1;
    g_hb[1][b * 512 + j] = __float2bfloat16(h_new - __bfloat162float(h1));
}

// =========================================================
// gates_body: hh gate partials -> planes 4-7 (shared by k_hh and k_big).
// =========================================================
__device__ void gates_body(int gid, const float* __restrict__ hsrc)
{
    __shared__ __align__(16) float Ws[16][260];
    __shared__ __align__(16) float hs[16][68];

    const int tid = threadIdx.x;
    const int r0   = (gid >> 2) * 128;
    const int koff = (gid & 3) * 128;
    float* gp = g_gates[4 + (gid & 3)];
    const int rg = tid & 15, bg = tid >> 4;
    const int wk = tid >> 5, wr = tid & 31;
    const int ab = tid >> 2, akq = tid & 3;
    ull acc[4][4] = {};

    float4 wreg[2], areg;
    #pragma unroll
    for (int q = 0; q < 2; q++)
        wreg[q] = *(const float4*)&g_WhhT[(size_t)(koff + wk + q * 8) * G4 + r0 + wr * 4];
    areg = *(const float4*)&hsrc[ab * 512 + koff + akq * 4];

    for (int c = 0; c < 8; c++) {
        #pragma unroll
        for (int q = 0; q < 2; q++) *(float4*)&Ws[wk + q * 8][wr * 4] = wreg[q];
        hs[akq * 4 + 0][ab] = areg.x; hs[akq * 4 + 1][ab] = areg.y;
        hs[akq * 4 + 2][ab] = areg.z; hs[akq * 4 + 3][ab] = areg.w;
        __syncthreads();
        if (c < 7) {
            int kb = koff + (c + 1) * 16;
            #pragma unroll
            for (int q = 0; q < 2; q++)
                wreg[q] = *(const float4*)&g_WhhT[(size_t)(kb + wk + q * 8) * G4 + r0 + wr * 4];
            areg = *(const float4*)&hsrc[ab * 512 + kb + akq * 4];
        }
        #pragma unroll
        for (int k = 0; k < 16; k++) {
            ulonglong2 W0 = *(const ulonglong2*)&Ws[k][4 * rg];
            ulonglong2 W1 = *(const ulonglong2*)&Ws[k][4 * rg + 64];
            float4 hv = *(const float4*)&hs[k][4 * bg];
            ull a0 = pk2(hv.x), a1 = pk2(hv.y), a2 = pk2(hv.z), a3 = pk2(hv.w);
            fma2(acc[0][0], W0.x, a0); fma2(acc[0][1], W0.y, a0);
            fma2(acc[0][2], W1.x, a0); fma2(acc[0][3], W1.y, a0);
            fma2(acc[1][0], W0.x, a1); fma2(acc[1][1], W0.y, a1);
            fma2(acc[1][2], W1.x, a1); fma2(acc[1][3], W1.y, a1);
            fma2(acc[2][0], W0.x, a2); fma2(acc[2][1], W0.y, a2);
            fma2(acc[2][2], W1.x, a2); fma2(acc[2][3], W1.y, a2);
            fma2(acc[3][0], W0.x, a3); fma2(acc[3][1], W0.y, a3);
            fma2(acc[3][2], W1.x, a3); fma2(acc[3][3], W1.y, a3);
        }
        __syncthreads();
    }
    #pragma unroll
    for (int bb = 0; bb < 4; bb++) {
        int b = 4 * bg + bb;
        ulonglong2 o0, o1;
        o0.x = acc[bb][0]; o0.y = acc[bb][1];
        o1.x = acc[bb][2]; o1.y = acc[bb][3];
        *(ulonglong2*)&gp[(size_t)b * G4 + r0 + 4 * rg]      = o0;
        *(ulonglong2*)&gp[(size_t)b * G4 + r0 + 4 * rg + 64] = o1;
    }
}

__global__ __launch_bounds__(256) void k_hh(int t, const float* __restrict__ features)
{
    gates_body(blockIdx.x, (t < 0) ? features : g_h[t & 1]);
}

// =========================================================
// k_big: bids 0..249 = logits(t) via HMMA bf16 3-pass split (128v x 64b),
//        bids 250..313 = hh gates for t+1 (skipped at t = T-1).
// Dynamic smem: double-buffered (W1 16K | W2 16K | H1 8K | H2 8K) = 2 x 48K.
// =========================================================
#define DSM_STRIDE 49152
#define DSM_W1 0
#define DSM_W2 16384
#define DSM_H1 32768
#define DSM_H2 40960
#define DSM_TOT (2 * DSM_STRIDE)

__device__ __forceinline__ void stage_chunk(uint32_t sb, int buf, int vb, int k0, int tid)
{
    uint32_t base = sb + buf * DSM_STRIDE;
    #pragma unroll
    for (int q = 0; q < 4; q++) {
        int idx = tid + q * 256;
        int v = idx >> 3, uu = idx & 7;
        uint32_t dst = SW128((uint32_t)(v * 128 + uu * 16));
        size_t so = (size_t)(vb + v) * 512 + k0 + uu * 8;
        cpasync16(base + DSM_W1 + dst, g_Wb1 + so);
        cpasync16(base + DSM_W2 + dst, g_Wb2 + so);
    }
    #pragma unroll
    for (int q = 0; q < 2; q++) {
        int idx = tid + q * 256;
        int b = idx >> 3, uu = idx & 7;
        uint32_t dst = SW128((uint32_t)(b * 128 + uu * 16));
        size_t so = (size_t)b * 512 + k0 + uu * 8;
        cpasync16(base + DSM_H1 + dst, g_hb[0] + so);
        cpasync16(base + DSM_H2 + dst, g_hb[1] + so);
    }
    asm volatile("cp.async.commit_group;" ::: "memory");
}

__global__ __launch_bounds__(256) void k_big(
    int t, const float* __restrict__ lin_b, float* __restrict__ out)
{
    const int tid = threadIdx.x;
    const int bid = blockIdx.x;

    if (bid >= 250) {                 // hh gates for t+1
        if (t >= T_ - 1) return;
        gates_body(bid - 250, g_h[t & 1]);
        return;
    }

    extern __shared__ char dsm[];
    __shared__ ull s_amax[64];
    const uint32_t sb = smem_u32(dsm);
    const int wid = tid >> 5, lid = tid & 31;
    const int vb = bid * 128;

    if (tid < 64) s_amax[tid] = 0ull;
    if (bid == 0 && tid < 64) g_amax[(t + 1) & 1][tid] = 0ull;

    // lane-role constants for ldmatrix addressing
    const int sel = lid >> 3, row = lid & 7;
    const int aV  = 16 * wid + ((sel & 1) << 3) + row;   // A: matrix -> v row
    const int aKo = (sel >> 1) << 3;                     // A: k offset 0/8
    const int bB  = ((sel >> 1) << 3) + row;             // B: row within 16-b pair
    const int bKo = (sel & 1) << 3;                      // B: k offset 0/8

    float acc[8][4] = {};

    stage_chunk(sb, 0, vb, 0, tid);
    for (int c = 0; c < 8; c++) {
        if (c < 7) {
            stage_chunk(sb, (c + 1) & 1, vb, (c + 1) * 64, tid);
            asm volatile("cp.async.wait_group 1;" ::: "memory");
        } else {
            asm volatile("cp.async.wait_group 0;" ::: "memory");
        }
        __syncthreads();
        const uint32_t base = sb + (c & 1) * DSM_STRIDE;

        #pragma unroll
        for (int kk = 0; kk < 64; kk += 16) {
            uint32_t a1[4], a2[4];
            uint32_t aoff = SW128((uint32_t)(aV * 128 + (kk + aKo) * 2));
            ldsm4(a1, base + DSM_W1 + aoff);
            ldsm4(a2, base + DSM_W2 + aoff);
            #pragma unroll
            for (int jp = 0; jp < 4; jp++) {
                uint32_t b1[4], b2[4];
                uint32_t boff = SW128((uint32_t)((16 * jp + bB) * 128 + (kk + bKo) * 2));
                ldsm4(b1, base + DSM_H1 + boff);
                ldsm4(b2, base + DSM_H2 + boff);
                mma16816(acc[2 * jp],     a1, b1[0], b1[1]);
                mma16816(acc[2 * jp + 1], a1, b1[2], b1[3]);
                mma16816(acc[2 * jp],     a1, b2[0], b2[1]);
                mma16816(acc[2 * jp + 1], a1, b2[2], b2[3]);
                mma16816(acc[2 * jp],     a2, b1[0], b1[1]);
                mma16816(acc[2 * jp + 1], a2, b1[2], b1[3]);
            }
        }
        __syncthreads();
    }

    // epilogue: bias, store, argmax
    const int qrow = lid >> 2, qcol = lid & 3;
    const int v0 = vb + 16 * wid + qrow;
    const int v1 = v0 + 8;
    const float bi0 = lin_b[v0], bi1 = lin_b[v1];

    #pragma unroll
    for (int j = 0; j < 8; j++) {
        int blo = 8 * j + 2 * qcol, bhi = blo + 1;
        float c0 = acc[j][0] + bi0;
        float c1 = acc[j][1] + bi0;
        float c2 = acc[j][2] + bi1;
        float c3 = acc[j][3] + bi1;
        out[((size_t)blo * T_ + t) * V_ + v0] = c0;
        out[((size_t)bhi * T_ + t) * V_ + v0] = c1;
        out[((size_t)blo * T_ + t) * V_ + v1] = c2;
        out[((size_t)bhi * T_ + t) * V_ + v1] = c3;

        ull klo = ((ull)fkey(c0) << 32) | (ull)(0x7FFFFFFFu - (unsigned)v0);
        ull k2  = ((ull)fkey(c2) << 32) | (ull)(0x7FFFFFFFu - (unsigned)v1);
        if (k2 > klo) klo = k2;
        ull khi = ((ull)fkey(c1) << 32) | (ull)(0x7FFFFFFFu - (unsigned)v0);
        k2      = ((ull)fkey(c3) << 32) | (ull)(0x7FFFFFFFu - (unsigned)v1);
        if (k2 > khi) khi = k2;
        #pragma unroll
        for (int s = 4; s < 32; s <<= 1) {
            ull o1 = __shfl_xor_sync(0xFFFFFFFFu, klo, s); if (o1 > klo) klo = o1;
            ull o2 = __shfl_xor_sync(0xFFFFFFFFu, khi, s); if (o2 > khi) khi = o2;
        }
        if (lid < 4) {
            atomicMax(&s_amax[blo], klo);
            atomicMax(&s_amax[bhi], khi);
        }
    }
    __syncthreads();
    if (tid < 64) atomicMax(&g_amax[t & 1][tid], s_amax[tid]);
}

// =========================================================
extern "C" void kernel_launch(void* const* d_in, const int* in_sizes, int n_in,
                              void* d_out, int out_size)
{
    const float* features = (const float*)d_in[0];
    const void*  captions = d_in[1];
    int off = (in_sizes[2] == V_ * E_) ? 0 : 1;   // 'lengths' may be materialized
    const float* embed = (const float*)d_in[2 + off];
    const float* W_ih  = (const float*)d_in[3 + off];
    const float* W_hh  = (const float*)d_in[4 + off];
    const float* b_ih  = (const float*)d_in[5 + off];
    const float* b_hh  = (const float*)d_in[6 + off];
    const float* lin_W = (const float*)d_in[7 + off];
    const float* lin_b = (const float*)d_in[8 + off];
    float* out = (float*)d_out;
    (void)n_in; (void)out_size;

    cudaFuncSetAttribute(k_big, cudaFuncAttributeMaxDynamicSharedMemorySize, DSM_TOT);

    // one-time prologue
    kT<<<dim3(64, 16), dim3(32, 8)>>>(W_ih, 1, 2048);
    kT<<<dim3(64, 16), dim3(32, 8)>>>(W_hh, 2, 2048);
    k_split<<<64000, 256>>>(lin_W);
    k_hh<<<64, 256>>>(-1, features);     // hh planes for t=0 (h(-1) = features)

    for (int t = 0; t < T_; t++) {
        k_ih<<<dim3(32, 4, 2), 256>>>(t, captions, embed);
        k_update<<<128, 256>>>(t, features, b_ih, b_hh);
        k_big<<<314, 256, DSM_TOT>>>(t, lin_b, out);
    }
}

// round 8
// speedup vs baseline: 8.9633x; 1.2350x over previous
#include <cuda_runtime.h>
#include <cuda_bf16.h>
#include <math.h>
#include <stdint.h>

#define B_  64
#define E_  512
#define H_  512
#define V_  32000
#define T_  32
#define G4  2048   // 4*H

typedef unsigned long long ull;

// ---------------- persistent device state ----------------
__device__ __align__(16) float g_h[2][B_ * H_];     // double-buffered hidden state
__device__ __align__(16) float g_c[B_ * H_];        // cell state
__device__ __align__(16) float g_gates[4][B_ * G4]; // planes: ih-k0, ih-k1, hh-k0, hh-k1
__device__ ull g_amax[2][B_];                       // packed argmax accumulators
// bf16 2-term splits
__device__ __align__(16) __nv_bfloat16 g_Wb1[(size_t)V_ * 512];   // lin_W hi
__device__ __align__(16) __nv_bfloat16 g_Wb2[(size_t)V_ * 512];   // lin_W lo
__device__ __align__(16) __nv_bfloat16 g_Ib1[2048 * 512];         // W_ih hi
__device__ __align__(16) __nv_bfloat16 g_Ib2[2048 * 512];         // W_ih lo
__device__ __align__(16) __nv_bfloat16 g_Hb1[2048 * 512];         // W_hh hi
__device__ __align__(16) __nv_bfloat16 g_Hb2[2048 * 512];         // W_hh lo
__device__ __align__(16) __nv_bfloat16 g_hb[2][B_ * 512];         // h(t) splits [term][b*512+k]

__device__ __forceinline__ unsigned fkey(float f) {
    unsigned u = __float_as_uint(f);
    return (u & 0x80000000u) ? ~u : (u | 0x80000000u);
}
__device__ __forceinline__ uint32_t smem_u32(const void* p) {
    uint32_t a;
    asm("{ .reg .u64 t; cvta.to.shared.u64 t, %1; cvt.u32.u64 %0, t; }" : "=r"(a) : "l"(p));
    return a;
}
__device__ __forceinline__ void ldsm4(uint32_t* r, uint32_t addr) {
    asm volatile("ldmatrix.sync.aligned.m8n8.x4.shared.b16 {%0,%1,%2,%3}, [%4];"
        : "=r"(r[0]), "=r"(r[1]), "=r"(r[2]), "=r"(r[3]) : "r"(addr));
}
__device__ __forceinline__ void mma16816(float* d, const uint32_t* a, uint32_t b0, uint32_t b1) {
    asm volatile("mma.sync.aligned.m16n8k16.row.col.f32.bf16.bf16.f32 "
        "{%0,%1,%2,%3}, {%4,%5,%6,%7}, {%8,%9}, {%0,%1,%2,%3};"
        : "+f"(d[0]), "+f"(d[1]), "+f"(d[2]), "+f"(d[3])
        : "r"(a[0]), "r"(a[1]), "r"(a[2]), "r"(a[3]), "r"(b0), "r"(b1));
}
__device__ __forceinline__ void cpasync16(uint32_t dst, const void* src) {
    asm volatile("cp.async.cg.shared.global [%0], [%1], 16;" :: "r"(dst), "l"(src));
}
#define SW128(o) ((o) ^ (((o) >> 3) & 0x70))

// Dynamic smem layout (per buffer): W1 16K | W2 16K | H1 8K | H2 8K
#define DSM_STRIDE 49152
#define DSM_W1 0
#define DSM_W2 16384
#define DSM_H1 32768
#define DSM_H2 40960
#define DSM_TOT (2 * DSM_STRIDE)

// =========================================================
// k_splitall: one prologue kernel producing every bf16 split.
//  bids [0,64000): lin_W ; [64000,68096): W_ih ; [68096,72192): W_hh ;
//  [72192,72320): features -> g_hb (h(-1)).
// =========================================================
__global__ __launch_bounds__(256) void k_splitall(
    const float* __restrict__ lin_W, const float* __restrict__ W_ih,
    const float* __restrict__ W_hh,  const float* __restrict__ features)
{
    const int bid = blockIdx.x;
    const int tid = threadIdx.x;
    if (bid < 64000) {
        size_t i = (size_t)bid * 256 + tid;
        float w = lin_W[i];
        __nv_bfloat16 h1 = __float2bfloat16(w);
        g_Wb1[i] = h1;
        g_Wb2[i] = __float2bfloat16(w - __bfloat162float(h1));
    } else if (bid < 68096) {
        int i = (bid - 64000) * 256 + tid;
        float w = W_ih[i];
        __nv_bfloat16 h1 = __float2bfloat16(w);
        g_Ib1[i] = h1;
        g_Ib2[i] = __float2bfloat16(w - __bfloat162float(h1));
    } else if (bid < 72192) {
        int i = (bid - 68096) * 256 + tid;
        float w = W_hh[i];
        __nv_bfloat16 h1 = __float2bfloat16(w);
        g_Hb1[i] = h1;
        g_Hb2[i] = __float2bfloat16(w - __bfloat162float(h1));
    } else {
        int i = (bid - 72192) * 256 + tid;
        float f = features[i];
        __nv_bfloat16 h1 = __float2bfloat16(f);
        g_hb[0][i] = h1;
        g_hb[1][i] = __float2bfloat16(f - __bfloat162float(h1));
    }
}

// =========================================================
// k_prep: gate pre-activation partials via HMMA 3-pass bf16 split.
// grid 64: bid -> wsel = bid>>5 (0: W_ih@x, 1: W_hh@h), sub = bid&31,
//   rblk = sub>>1 (128-row block of 2048), khalf = sub&1 (256-k half).
// Output plane = wsel*2 + khalf. Block tile 128r x 64b x 256k (4 chunks of 64k).
// =========================================================
__global__ __launch_bounds__(256) void k_prep(
    int t, const void* __restrict__ captions, const float* __restrict__ embed)
{
    extern __shared__ char dsm[];
    __shared__ int stok[B_];
    const uint32_t sb = smem_u32(dsm);
    const int tid = threadIdx.x;
    const int bid = blockIdx.x;
    const int wid = tid >> 5, lid = tid & 31;

    const int wsel  = bid >> 5;
    const int sub   = bid & 31;
    const int rb    = (sub >> 1) * 128;
    const int kbase = (sub & 1) * 256;

    if (t == 0 && bid == 0 && tid < 128)
        g_amax[tid >> 6][tid & 63] = 0ull;

    if (wsel == 0 && tid < B_) {
        int tok;
        if (t == 0) {
            const int* ci = (const int*)captions;
            bool is64 = true;
            #pragma unroll
            for (int i = 1; i < 32; i += 2) if (ci[i]) is64 = false;
            tok = is64 ? (int)((const long long*)captions)[tid] : ci[tid];
        } else {
            ull pk = g_amax[(t + 1) & 1][tid];
            tok = (int)(0x7FFFFFFFu - (unsigned)(pk & 0xFFFFFFFFull));
        }
        stok[tid] = tok;
    }
    __syncthreads();

    const __nv_bfloat16* A1 = wsel ? g_Hb1 : g_Ib1;
    const __nv_bfloat16* A2 = wsel ? g_Hb2 : g_Ib2;

    // ---- staging ----
    auto stage = [&](int buf, int c) {
        const int k0 = kbase + c * 64;
        uint32_t base = sb + buf * DSM_STRIDE;
        #pragma unroll
        for (int q = 0; q < 4; q++) {
            int idx = tid + q * 256;
            int r = idx >> 3, uu = idx & 7;
            uint32_t dst = SW128((uint32_t)(r * 128 + uu * 16));
            size_t so = (size_t)(rb + r) * 512 + k0 + uu * 8;
            cpasync16(base + DSM_W1 + dst, A1 + so);
            cpasync16(base + DSM_W2 + dst, A2 + so);
        }
        if (wsel) {
            #pragma unroll
            for (int q = 0; q < 2; q++) {
                int idx = tid + q * 256;
                int b = idx >> 3, uu = idx & 7;
                uint32_t dst = SW128((uint32_t)(b * 128 + uu * 16));
                size_t so = (size_t)b * 512 + k0 + uu * 8;
                cpasync16(base + DSM_H1 + dst, g_hb[0] + so);
                cpasync16(base + DSM_H2 + dst, g_hb[1] + so);
            }
            asm volatile("cp.async.commit_group;" ::: "memory");
        } else {
            asm volatile("cp.async.commit_group;" ::: "memory");
            // gather embed rows, split fp32 -> bf16 hi/lo, STS
            #pragma unroll
            for (int q = 0; q < 4; q++) {
                int idx = tid + q * 256;
                int b = idx >> 4, kk = (idx & 15) * 4;
                float4 x = *(const float4*)(embed + (size_t)stok[b] * E_ + k0 + kk);
                __nv_bfloat16 hx = __float2bfloat16(x.x), hy = __float2bfloat16(x.y);
                __nv_bfloat16 hz = __float2bfloat16(x.z), hw = __float2bfloat16(x.w);
                __nv_bfloat162 hi0; hi0.x = hx; hi0.y = hy;
                __nv_bfloat162 hi1; hi1.x = hz; hi1.y = hw;
                __nv_bfloat162 lo0, lo1;
                lo0.x = __float2bfloat16(x.x - __bfloat162float(hx));
                lo0.y = __float2bfloat16(x.y - __bfloat162float(hy));
                lo1.x = __float2bfloat16(x.z - __bfloat162float(hz));
                lo1.y = __float2bfloat16(x.w - __bfloat162float(hw));
                uint32_t dst = SW128((uint32_t)(b * 128 + kk * 2));
                ull hp, lp;
                memcpy(&hp, &hi0, 4); memcpy(((char*)&hp) + 4, &hi1, 4);
                memcpy(&lp, &lo0, 4); memcpy(((char*)&lp) + 4, &lo1, 4);
                *(ull*)(dsm + buf * DSM_STRIDE + DSM_H1 + dst) = hp;
                *(ull*)(dsm + buf * DSM_STRIDE + DSM_H2 + dst) = lp;
            }
        }
    };

    // lane-role constants
    const int sel = lid >> 3, row = lid & 7;
    const int aV  = 16 * wid + ((sel & 1) << 3) + row;
    const int aKo = (sel >> 1) << 3;
    const int bB  = ((sel >> 1) << 3) + row;
    const int bKo = (sel & 1) << 3;

    float acc[8][4] = {};

    stage(0, 0);
    for (int c = 0; c < 4; c++) {
        if (c < 3) {
            stage((c + 1) & 1, c + 1);
            asm volatile("cp.async.wait_group 1;" ::: "memory");
        } else {
            asm volatile("cp.async.wait_group 0;" ::: "memory");
        }
        __syncthreads();
        const uint32_t base = sb + (c & 1) * DSM_STRIDE;

        #pragma unroll
        for (int kk = 0; kk < 64; kk += 16) {
            uint32_t a1[4], a2[4];
            uint32_t aoff = SW128((uint32_t)(aV * 128 + (kk + aKo) * 2));
            ldsm4(a1, base + DSM_W1 + aoff);
            ldsm4(a2, base + DSM_W2 + aoff);
            #pragma unroll
            for (int jp = 0; jp < 4; jp++) {
                uint32_t b1[4], b2[4];
                uint32_t boff = SW128((uint32_t)((16 * jp + bB) * 128 + (kk + bKo) * 2));
                ldsm4(b1, base + DSM_H1 + boff);
                ldsm4(b2, base + DSM_H2 + boff);
                mma16816(acc[2 * jp],     a1, b1[0], b1[1]);
                mma16816(acc[2 * jp + 1], a1, b1[2], b1[3]);
                mma16816(acc[2 * jp],     a1, b2[0], b2[1]);
                mma16816(acc[2 * jp + 1], a1, b2[2], b2[3]);
                mma16816(acc[2 * jp],     a2, b1[0], b1[1]);
                mma16816(acc[2 * jp + 1], a2, b1[2], b1[3]);
            }
        }
        __syncthreads();
    }

    // epilogue: write fp32 partials into plane
    float* gp = g_gates[wsel * 2 + (sub & 1)];
    const int qrow = lid >> 2, qcol = lid & 3;
    const int r0 = rb + 16 * wid + qrow;
    const int r1 = r0 + 8;
    #pragma unroll
    for (int j = 0; j < 8; j++) {
        int blo = 8 * j + 2 * qcol, bhi = blo + 1;
        gp[(size_t)blo * G4 + r0] = acc[j][0];
        gp[(size_t)bhi * G4 + r0] = acc[j][1];
        gp[(size_t)blo * G4 + r1] = acc[j][2];
        gp[(size_t)bhi * G4 + r1] = acc[j][3];
    }
}

// =========================================================
// k_update: sum 4 planes + biases, LSTM nonlin, write h + bf16 splits.
// =========================================================
__global__ __launch_bounds__(256) void k_update(
    int t, const float* __restrict__ features,
    const float* __restrict__ b_ih, const float* __restrict__ b_hh)
{
    int idx = blockIdx.x * 256 + threadIdx.x;
    int b = idx >> 9, j = idx & 511;
    const int base = b * G4;

    float z[4];
    #pragma unroll
    for (int g = 0; g < 4; g++) {
        int o = base + j + g * 512;
        z[g] = b_ih[j + g * 512] + b_hh[j + g * 512]
             + g_gates[0][o] + g_gates[1][o] + g_gates[2][o] + g_gates[3][o];
    }
    float i_ = 1.0f / (1.0f + expf(-z[0]));
    float f_ = 1.0f / (1.0f + expf(-z[1]));
    float gg = tanhf(z[2]);
    float o_ = 1.0f / (1.0f + expf(-z[3]));

    float c_old = (t == 0) ? features[b * H_ + j] : g_c[b * H_ + j];
    float c_new = f_ * c_old + i_ * gg;
    float h_new = o_ * tanhf(c_new);

    g_c[b * H_ + j]        = c_new;
    g_h[t & 1][b * H_ + j] = h_new;

    __nv_bfloat16 h1 = __float2bfloat16(h_new);
    g_hb[0][b * 512 + j] = h1;
    g_hb[1][b * 512 + j] = __float2bfloat16(h_new - __bfloat162float(h1));
}

// =========================================================
// k_big: logits via HMMA bf16 3-pass split. grid 250, 256 thr.
// Block: 128v x 64b x 512k (8 chunks of 64k), double-buffered cp.async.
// =========================================================
__device__ __forceinline__ void stage_chunk(uint32_t sb, int buf, int vb, int k0, int tid)
{
    uint32_t base = sb + buf * DSM_STRIDE;
    #pragma unroll
    for (int q = 0; q < 4; q++) {
        int idx = tid + q * 256;
        int v = idx >> 3, uu = idx & 7;
        uint32_t dst = SW128((uint32_t)(v * 128 + uu * 16));
        size_t so = (size_t)(vb + v) * 512 + k0 + uu * 8;
        cpasync16(base + DSM_W1 + dst, g_Wb1 + so);
        cpasync16(base + DSM_W2 + dst, g_Wb2 + so);
    }
    #pragma unroll
    for (int q = 0; q < 2; q++) {
        int idx = tid + q * 256;
        int b = idx >> 3, uu = idx & 7;
        uint32_t dst = SW128((uint32_t)(b * 128 + uu * 16));
        size_t so = (size_t)b * 512 + k0 + uu * 8;
        cpasync16(base + DSM_H1 + dst, g_hb[0] + so);
        cpasync16(base + DSM_H2 + dst, g_hb[1] + so);
    }
    asm volatile("cp.async.commit_group;" ::: "memory");
}

__global__ __launch_bounds__(256) void k_big(
    int t, const float* __restrict__ lin_b, float* __restrict__ out)
{
    extern __shared__ char dsm[];
    __shared__ ull s_amax[64];
    const uint32_t sb = smem_u32(dsm);
    const int tid = threadIdx.x;
    const int bid = blockIdx.x;
    const int wid = tid >> 5, lid = tid & 31;
    const int vb = bid * 128;

    if (tid < 64) s_amax[tid] = 0ull;
    if (bid == 0 && tid < 64) g_amax[(t + 1) & 1][tid] = 0ull;

    const int sel = lid >> 3, row = lid & 7;
    const int aV  = 16 * wid + ((sel & 1) << 3) + row;
    const int aKo = (sel >> 1) << 3;
    const int bB  = ((sel >> 1) << 3) + row;
    const int bKo = (sel & 1) << 3;

    float acc[8][4] = {};

    stage_chunk(sb, 0, vb, 0, tid);
    for (int c = 0; c < 8; c++) {
        if (c < 7) {
            stage_chunk(sb, (c + 1) & 1, vb, (c + 1) * 64, tid);
            asm volatile("cp.async.wait_group 1;" ::: "memory");
        } else {
            asm volatile("cp.async.wait_group 0;" ::: "memory");
        }
        __syncthreads();
        const uint32_t base = sb + (c & 1) * DSM_STRIDE;

        #pragma unroll
        for (int kk = 0; kk < 64; kk += 16) {
            uint32_t a1[4], a2[4];
            uint32_t aoff = SW128((uint32_t)(aV * 128 + (kk + aKo) * 2));
            ldsm4(a1, base + DSM_W1 + aoff);
            ldsm4(a2, base + DSM_W2 + aoff);
            #pragma unroll
            for (int jp = 0; jp < 4; jp++) {
                uint32_t b1[4], b2[4];
                uint32_t boff = SW128((uint32_t)((16 * jp + bB) * 128 + (kk + bKo) * 2));
                ldsm4(b1, base + DSM_H1 + boff);
                ldsm4(b2, base + DSM_H2 + boff);
                mma16816(acc[2 * jp],     a1, b1[0], b1[1]);
                mma16816(acc[2 * jp + 1], a1, b1[2], b1[3]);
                mma16816(acc[2 * jp],     a1, b2[0], b2[1]);
                mma16816(acc[2 * jp + 1], a1, b2[2], b2[3]);
                mma16816(acc[2 * jp],     a2, b1[0], b1[1]);
                mma16816(acc[2 * jp + 1], a2, b1[2], b1[3]);
            }
        }
        __syncthreads();
    }

    // epilogue: bias, store, argmax
    const int qrow = lid >> 2, qcol = lid & 3;
    const int v0 = vb + 16 * wid + qrow;
    const int v1 = v0 + 8;
    const float bi0 = lin_b[v0], bi1 = lin_b[v1];

    #pragma unroll
    for (int j = 0; j < 8; j++) {
        int blo = 8 * j + 2 * qcol, bhi = blo + 1;
        float c0 = acc[j][0] + bi0;
        float c1 = acc[j][1] + bi0;
        float c2 = acc[j][2] + bi1;
        float c3 = acc[j][3] + bi1;
        out[((size_t)blo * T_ + t) * V_ + v0] = c0;
        out[((size_t)bhi * T_ + t) * V_ + v0] = c1;
        out[((size_t)blo * T_ + t) * V_ + v1] = c2;
        out[((size_t)bhi * T_ + t) * V_ + v1] = c3;

        ull klo = ((ull)fkey(c0) << 32) | (ull)(0x7FFFFFFFu - (unsigned)v0);
        ull k2  = ((ull)fkey(c2) << 32) | (ull)(0x7FFFFFFFu - (unsigned)v1);
        if (k2 > klo) klo = k2;
        ull khi = ((ull)fkey(c1) << 32) | (ull)(0x7FFFFFFFu - (unsigned)v0);
        k2      = ((ull)fkey(c3) << 32) | (ull)(0x7FFFFFFFu - (unsigned)v1);
        if (k2 > khi) khi = k2;
        #pragma unroll
        for (int s = 4; s < 32; s <<= 1) {
            ull o1 = __shfl_xor_sync(0xFFFFFFFFu, klo, s); if (o1 > klo) klo = o1;
            ull o2 = __shfl_xor_sync(0xFFFFFFFFu, khi, s); if (o2 > khi) khi = o2;
        }
        if (lid < 4) {
            atomicMax(&s_amax[blo], klo);
            atomicMax(&s_amax[bhi], khi);
        }
    }
    __syncthreads();
    if (tid < 64) atomicMax(&g_amax[t & 1][tid], s_amax[tid]);
}

// =========================================================
extern "C" void kernel_launch(void* const* d_in, const int* in_sizes, int n_in,
                              void* d_out, int out_size)
{
    const float* features = (const float*)d_in[0];
    const void*  captions = d_in[1];
    int off = (in_sizes[2] == V_ * E_) ? 0 : 1;   // 'lengths' may be materialized
    const float* embed = (const float*)d_in[2 + off];
    const float* W_ih  = (const float*)d_in[3 + off];
    const float* W_hh  = (const float*)d_in[4 + off];
    const float* b_ih  = (const float*)d_in[5 + off];
    const float* b_hh  = (const float*)d_in[6 + off];
    const float* lin_W = (const float*)d_in[7 + off];
    const float* lin_b = (const float*)d_in[8 + off];
    float* out = (float*)d_out;
    (void)n_in; (void)out_size;

    cudaFuncSetAttribute(k_big,  cudaFuncAttributeMaxDynamicSharedMemorySize, DSM_TOT);
    cudaFuncSetAttribute(k_prep, cudaFuncAttributeMaxDynamicSharedMemorySize, DSM_TOT);

    // one-time prologue: all bf16 splits (weights + h(-1)=features)
    k_splitall<<<72320, 256>>>(lin_W, W_ih, W_hh, features);

    for (int t = 0; t < T_; t++) {
        k_prep<<<64, 256, DSM_TOT>>>(t, captions, embed);
        k_update<<<128, 256>>>(t, features, b_ih, b_hh);
        k_big<<<250, 256, DSM_TOT>>>(t, lin_b, out);
    }
}